// round 1
// baseline (speedup 1.0000x reference)
#include <cuda_runtime.h>
#include <cstddef>

// Problem constants
#define BB   64
#define NN   300
#define DDIM 512
#define HH   8
#define DHD  64
#define LLAY 6
#define DFF  2048
#define MM   (BB*NN)   // 19200 rows

// ---------------- scratch (no allocation allowed) ----------------
__device__ float g_x [MM*DDIM];   // activations
__device__ float g_k [MM*DDIM];   // K=Q=V projection / ffn2 out
__device__ float g_o [MM*DDIM];   // attention output
__device__ float g_z [MM*DDIM];   // post-attn LN output
__device__ float g_h [(size_t)MM*DFF];  // Wo out (first MM*DDIM) then ffn hidden
__device__ float g_wp[DDIM*DDIM]; // packed Wk for current layer

// ---------------- embed: x = emb[tok] + pos ----------------
__global__ void embed_kernel(const int* __restrict__ tok,
                             const float* __restrict__ emb,
                             const float* __restrict__ pos,
                             float* __restrict__ x)
{
    int gid = blockIdx.x * blockDim.x + threadIdx.x;   // over MM*128 float4s
    int row = gid >> 7;
    int c   = gid & 127;
    int t   = tok[row];
    int n   = row % NN;
    float4 e = ((const float4*)emb)[(size_t)t * 128 + c];
    float4 p = ((const float4*)pos)[(size_t)n * 128 + c];
    float4 v = make_float4(e.x + p.x, e.y + p.y, e.z + p.z, e.w + p.w);
    ((float4*)x)[gid] = v;
}

// ---------------- pack Wk[l] (H,D,DH) -> (D, H*DH) row-major ----------------
__global__ void pack_wk(const float* __restrict__ wk, float* __restrict__ wp)
{
    int idx = blockIdx.x * blockDim.x + threadIdx.x;   // DDIM*DDIM
    int d = idx >> 9;
    int c = idx & 511;
    wp[idx] = wk[(size_t)(c >> 6) * (DDIM * DHD) + (size_t)d * DHD + (c & 63)];
}

// ---------------- SGEMM: C[M,N] = A[M,K] @ B[K,N] (+bias)(+relu) ----------------
// BM=BN=128, BK=8, TM=TN=8, 256 threads. All dims multiples of tile sizes.
__global__ __launch_bounds__(256)
void sgemm_kernel(const float* __restrict__ A, const float* __restrict__ Bm,
                  float* __restrict__ C, int Mdim, int Ndim, int Kdim,
                  const float* __restrict__ bias, int relu)
{
    __shared__ __align__(16) float As[8 * 132];   // padded: store-conflict free
    __shared__ __align__(16) float Bs[8 * 128];

    int tid  = threadIdx.x;
    int tcol = tid & 15;       // 0..15
    int trow = tid >> 4;       // 0..15
    int cRow = blockIdx.y * 128;
    int cCol = blockIdx.x * 128;

    const float* Ab = A + (size_t)cRow * Kdim;
    const float* Bb = Bm + cCol;

    float acc[8][8];
    #pragma unroll
    for (int i = 0; i < 8; i++)
        #pragma unroll
        for (int j = 0; j < 8; j++) acc[i][j] = 0.f;

    int arow = tid >> 1;          // 0..127
    int acol = (tid & 1) * 4;     // 0 or 4
    int brow = tid >> 5;          // 0..7
    int bcol = (tid & 31) * 4;    // 0..124

    for (int k0 = 0; k0 < Kdim; k0 += 8) {
        float4 av = *(const float4*)(Ab + (size_t)arow * Kdim + k0 + acol);
        As[(acol + 0) * 132 + arow] = av.x;
        As[(acol + 1) * 132 + arow] = av.y;
        As[(acol + 2) * 132 + arow] = av.z;
        As[(acol + 3) * 132 + arow] = av.w;
        float4 bv = *(const float4*)(Bb + (size_t)(k0 + brow) * Ndim + bcol);
        *(float4*)&Bs[brow * 128 + bcol] = bv;
        __syncthreads();

        #pragma unroll
        for (int kk = 0; kk < 8; kk++) {
            const float4* ap = (const float4*)&As[kk * 132 + trow * 8];
            const float4* bp = (const float4*)&Bs[kk * 128 + tcol * 8];
            float4 a0 = ap[0], a1 = ap[1];
            float4 b0 = bp[0], b1 = bp[1];
            float ra[8] = {a0.x, a0.y, a0.z, a0.w, a1.x, a1.y, a1.z, a1.w};
            float rb[8] = {b0.x, b0.y, b0.z, b0.w, b1.x, b1.y, b1.z, b1.w};
            #pragma unroll
            for (int i = 0; i < 8; i++)
                #pragma unroll
                for (int j = 0; j < 8; j++)
                    acc[i][j] += ra[i] * rb[j];
        }
        __syncthreads();
    }

    int crow = cRow + trow * 8;
    int ccol = cCol + tcol * 8;
    #pragma unroll
    for (int i = 0; i < 8; i++) {
        #pragma unroll
        for (int j = 0; j < 8; j += 4) {
            float4 v = make_float4(acc[i][j], acc[i][j+1], acc[i][j+2], acc[i][j+3]);
            if (bias) {
                float4 bb = *(const float4*)(bias + ccol + j);
                v.x += bb.x; v.y += bb.y; v.z += bb.z; v.w += bb.w;
            }
            if (relu) {
                v.x = fmaxf(v.x, 0.f); v.y = fmaxf(v.y, 0.f);
                v.z = fmaxf(v.z, 0.f); v.w = fmaxf(v.w, 0.f);
            }
            *(float4*)(C + (size_t)(crow + i) * Ndim + ccol + j) = v;
        }
    }
}

// ---------------- attention: per (b,h) CTA, full softmax, Q=K=V ----------------
// smem: Ks[320][65] (rows 300..319 zero), per-warp a[300]
#define KS_ROWS 320
#define KS_LD   65
#define ATTN_SMEM ((KS_ROWS*KS_LD + 8*NN) * 4)

__global__ __launch_bounds__(256)
void attn_kernel(const float* __restrict__ k, float* __restrict__ o)
{
    extern __shared__ float sm[];
    float* Ks = sm;                       // KS_ROWS * KS_LD
    float* Aw = sm + KS_ROWS * KS_LD;     // 8 * NN

    int bh = blockIdx.x;
    int b  = bh / HH, h = bh % HH;
    const float* kbase = k + (size_t)b * NN * DDIM + h * DHD;

    int tid  = threadIdx.x;
    int lane = tid & 31;
    int w    = tid >> 5;

    // load K head tile (zero-pad rows >= 300)
    for (int i = tid; i < KS_ROWS * DHD; i += 256) {
        int m = i >> 6, e = i & 63;
        Ks[m * KS_LD + e] = (m < NN) ? kbase[(size_t)m * DDIM + e] : 0.f;
    }
    __syncthreads();

    float* aw = Aw + w * NN;
    const float scale = 0.04419417382415922f;   // 1/sqrt(512)

    for (int n = w; n < NN; n += 8) {
        // ---- S = q . K^T : lane-per-key ----
        float sv[10];
        #pragma unroll
        for (int j = 0; j < 10; j++) sv[j] = 0.f;
        const float* qrow = Ks + n * KS_LD;
        #pragma unroll 4
        for (int e = 0; e < 64; e++) {
            float qe = qrow[e];                        // broadcast LDS
            #pragma unroll
            for (int j = 0; j < 10; j++)
                sv[j] += qe * Ks[(j * 32 + lane) * KS_LD + e];
        }
        // ---- softmax over 300 keys ----
        float mx = -1e30f;
        #pragma unroll
        for (int j = 0; j < 10; j++) {
            int m = j * 32 + lane;
            float s = (m < NN) ? sv[j] * scale : -1e30f;
            sv[j] = s;
            mx = fmaxf(mx, s);
        }
        #pragma unroll
        for (int off = 16; off; off >>= 1)
            mx = fmaxf(mx, __shfl_xor_sync(0xffffffffu, mx, off));
        float sum = 0.f;
        #pragma unroll
        for (int j = 0; j < 10; j++) {
            float ev = __expf(sv[j] - mx);
            sv[j] = ev;
            sum += ev;
        }
        #pragma unroll
        for (int off = 16; off; off >>= 1)
            sum += __shfl_xor_sync(0xffffffffu, sum, off);
        float inv = 1.f / sum;

        __syncwarp();
        #pragma unroll
        for (int j = 0; j < 10; j++) {
            int m = j * 32 + lane;
            if (m < NN) aw[m] = sv[j] * inv;
        }
        __syncwarp();

        // ---- O = a @ K : lane-per-channel ----
        float o0 = 0.f, o1 = 0.f;
        #pragma unroll 4
        for (int m = 0; m < NN; m++) {
            float a = aw[m];                           // broadcast LDS
            o0 += a * Ks[m * KS_LD + lane];
            o1 += a * Ks[m * KS_LD + 32 + lane];
        }
        float* orow = o + (size_t)(b * NN + n) * DDIM + h * DHD;
        orow[lane]      = o0;
        orow[lane + 32] = o1;
        __syncwarp();
    }
}

// ---------------- residual + LayerNorm: out = LN(a+b)*gamma+beta ----------------
__global__ __launch_bounds__(256)
void ln_kernel(const float* __restrict__ a, const float* __restrict__ b,
               const float* __restrict__ gamma, const float* __restrict__ beta,
               float* __restrict__ out)
{
    int w    = threadIdx.x >> 5;
    int lane = threadIdx.x & 31;
    int row  = blockIdx.x * 8 + w;

    const float4* a4 = (const float4*)(a + (size_t)row * DDIM);
    const float4* b4 = (const float4*)(b + (size_t)row * DDIM);
    float4 v[4];
    float s1 = 0.f, s2 = 0.f;
    #pragma unroll
    for (int j = 0; j < 4; j++) {
        float4 av = a4[j * 32 + lane];
        float4 bv = b4[j * 32 + lane];
        float4 t = make_float4(av.x + bv.x, av.y + bv.y, av.z + bv.z, av.w + bv.w);
        v[j] = t;
        s1 += t.x + t.y + t.z + t.w;
        s2 += t.x * t.x + t.y * t.y + t.z * t.z + t.w * t.w;
    }
    #pragma unroll
    for (int off = 16; off; off >>= 1) {
        s1 += __shfl_xor_sync(0xffffffffu, s1, off);
        s2 += __shfl_xor_sync(0xffffffffu, s2, off);
    }
    float mean = s1 * (1.f / DDIM);
    float var  = s2 * (1.f / DDIM) - mean * mean;
    float rs   = rsqrtf(var + 1e-5f);

    const float4* g4  = (const float4*)gamma;
    const float4* be4 = (const float4*)beta;
    float4* o4 = (float4*)(out + (size_t)row * DDIM);
    #pragma unroll
    for (int j = 0; j < 4; j++) {
        float4 g = g4[j * 32 + lane];
        float4 be = be4[j * 32 + lane];
        float4 t = v[j];
        float4 r;
        r.x = (t.x - mean) * rs * g.x + be.x;
        r.y = (t.y - mean) * rs * g.y + be.y;
        r.z = (t.z - mean) * rs * g.z + be.z;
        r.w = (t.w - mean) * rs * g.w + be.w;
        o4[j * 32 + lane] = r;
    }
}

// ---------------- launcher ----------------
extern "C" void kernel_launch(void* const* d_in, const int* in_sizes, int n_in,
                              void* d_out, int out_size)
{
    const int*   tokens = (const int*)  d_in[0];
    const float* emb    = (const float*)d_in[1];
    const float* pos    = (const float*)d_in[2];
    const float* Wk     = (const float*)d_in[3];
    const float* Wo     = (const float*)d_in[4];
    const float* W1     = (const float*)d_in[5];
    const float* b1     = (const float*)d_in[6];
    const float* W2     = (const float*)d_in[7];
    const float* b2     = (const float*)d_in[8];
    const float* gamma  = (const float*)d_in[9];
    const float* beta   = (const float*)d_in[10];

    float *x, *k, *o, *z, *h, *wp;
    cudaGetSymbolAddress((void**)&x,  g_x);
    cudaGetSymbolAddress((void**)&k,  g_k);
    cudaGetSymbolAddress((void**)&o,  g_o);
    cudaGetSymbolAddress((void**)&z,  g_z);
    cudaGetSymbolAddress((void**)&h,  g_h);
    cudaGetSymbolAddress((void**)&wp, g_wp);

    cudaFuncSetAttribute(attn_kernel,
                         cudaFuncAttributeMaxDynamicSharedMemorySize, ATTN_SMEM);

    embed_kernel<<<(MM * 128) / 256, 256>>>(tokens, emb, pos, x);

    for (int l = 0; l < LLAY; l++) {
        pack_wk<<<(DDIM * DDIM) / 256, 256>>>(Wk + (size_t)l * HH * DDIM * DHD, wp);

        // K = X @ Wpack   [MM, 512]
        sgemm_kernel<<<dim3(DDIM / 128, MM / 128), 256>>>(
            x, wp, k, MM, DDIM, DDIM, nullptr, 0);

        // attention -> o  [MM, 512] (already [B,N,H*DH] layout)
        attn_kernel<<<BB * HH, 256, ATTN_SMEM>>>(k, o);

        // o @ Wo -> h (first MM*512 of g_h)
        sgemm_kernel<<<dim3(DDIM / 128, MM / 128), 256>>>(
            o, Wo + (size_t)l * DDIM * DDIM, h, MM, DDIM, DDIM, nullptr, 0);

        // z = LN(h + x)
        ln_kernel<<<MM / 8, 256>>>(h, x, gamma + (size_t)l * DDIM,
                                   beta + (size_t)l * DDIM, z);

        // h = relu(z @ W1 + b1)   [MM, 2048]
        sgemm_kernel<<<dim3(DFF / 128, MM / 128), 256>>>(
            z, W1 + (size_t)l * DDIM * DFF, h, MM, DFF, DDIM,
            b1 + (size_t)l * DFF, 1);

        // k = h @ W2 + b2   [MM, 512]  (reuse k buffer)
        sgemm_kernel<<<dim3(DDIM / 128, MM / 128), 256>>>(
            h, W2 + (size_t)l * DFF * DDIM, k, MM, DDIM, DFF,
            b2 + (size_t)l * DDIM, 0);

        // x = LN(k + z)  (last layer writes straight to d_out)
        float* dst = (l == LLAY - 1) ? (float*)d_out : x;
        ln_kernel<<<MM / 8, 256>>>(k, z, gamma + (size_t)l * DDIM,
                                   beta + (size_t)l * DDIM, dst);
    }
}

// round 2
// speedup vs baseline: 2.0258x; 2.0258x over previous
#include <cuda_runtime.h>
#include <cstddef>
#include <cstdint>

// Problem constants
#define BB   64
#define NN   300
#define DDIM 512
#define HH   8
#define DHD  64
#define LLAY 6
#define DFF  2048
#define MM   (BB*NN)   // 19200 rows

// ---------------- scratch (no allocation allowed) ----------------
__device__ float g_x [MM*DDIM];   // activations
__device__ float g_k [MM*DDIM];   // K=Q=V projection / ffn2 out
__device__ float g_o [MM*DDIM];   // attention output
__device__ float g_z [MM*DDIM];   // post-attn LN output
__device__ float g_h [(size_t)MM*DFF];  // Wo out (first MM*DDIM) then ffn hidden
__device__ float g_wp[DDIM*DDIM]; // packed Wk for current layer

// ---------------- embed: x = emb[tok] + pos ----------------
__global__ void embed_kernel(const int* __restrict__ tok,
                             const float* __restrict__ emb,
                             const float* __restrict__ pos,
                             float* __restrict__ x)
{
    int gid = blockIdx.x * blockDim.x + threadIdx.x;   // over MM*128 float4s
    int row = gid >> 7;
    int c   = gid & 127;
    int t   = tok[row];
    int n   = row % NN;
    float4 e = ((const float4*)emb)[(size_t)t * 128 + c];
    float4 p = ((const float4*)pos)[(size_t)n * 128 + c];
    float4 v = make_float4(e.x + p.x, e.y + p.y, e.z + p.z, e.w + p.w);
    ((float4*)x)[gid] = v;
}

// ---------------- pack Wk[l] (H,D,DH) -> (D, H*DH) row-major ----------------
__global__ void pack_wk(const float* __restrict__ wk, float* __restrict__ wp)
{
    int idx = blockIdx.x * blockDim.x + threadIdx.x;   // DDIM*DDIM
    int d = idx >> 9;
    int c = idx & 511;
    wp[idx] = wk[(size_t)(c >> 6) * (DDIM * DHD) + (size_t)d * DHD + (c & 63)];
}

// ---------------- tf32 tensor-core GEMM ----------------
// C[M,N] = A[M,K] @ B[K,N] (+bias)(+relu), fp32 in/out, tf32 mma accumulate fp32.
// BM=BN=128, BK=16, 256 threads = 8 warps (2x4), warp tile 64x32,
// mma.m16n8k8: 4x4 mma tiles per warp per k8-substep. cp.async double buffer.

#define ASTRIDE 20    // As row stride (floats): banks (20*g+tig)%32 all distinct
#define BSTRIDE 136   // Bs row stride (floats): banks (8*tig+g) all distinct

__device__ __forceinline__ uint32_t f2tf(float x) {
    uint32_t r;
    asm("cvt.rna.tf32.f32 %0, %1;" : "=r"(r) : "f"(x));
    return r;
}

__device__ __forceinline__ void cp_async16(uint32_t smem_addr, const void* gptr) {
    asm volatile("cp.async.cg.shared.global [%0], [%1], 16;\n"
                 :: "r"(smem_addr), "l"(gptr));
}

__global__ __launch_bounds__(256)
void mma_gemm_kernel(const float* __restrict__ A, const float* __restrict__ Bm,
                     float* __restrict__ C, int Mdim, int Ndim, int Kdim,
                     const float* __restrict__ bias, int relu)
{
    __shared__ __align__(16) float As[2][128][ASTRIDE];
    __shared__ __align__(16) float Bs[2][16][BSTRIDE];

    const int tid  = threadIdx.x;
    const int lane = tid & 31;
    const int w    = tid >> 5;
    const int g    = lane >> 2;     // group id 0..7
    const int tig  = lane & 3;      // thread in group 0..3

    const int warp_m = (w & 1) * 64;        // 0 or 64
    const int warp_n = (w >> 1) * 32;       // 0,32,64,96

    const int cRow = blockIdx.y * 128;
    const int cCol = blockIdx.x * 128;

    // global->smem copy indices (each thread: 2 x 16B for A, 2 x 16B for B)
    const int am0 = (tid)        >> 2;        // A chunk row (chunks c = tid, tid+256)
    const int ak0 = (tid & 3) * 4;
    const int am1 = (tid + 256)  >> 2;
    const int ak1 = ak0;                      // (tid+256)&3 == tid&3
    const int bk0 = tid >> 5;                 // B rows 0..7 then 8..15
    const int bn0 = (tid & 31) * 4;
    const int bk1 = bk0 + 8;

    const float* Ag = A + (size_t)cRow * Kdim;
    const float* Bg = Bm + cCol;

    float acc[4][4][4];
    #pragma unroll
    for (int mi = 0; mi < 4; mi++)
        #pragma unroll
        for (int ni = 0; ni < 4; ni++)
            #pragma unroll
            for (int r = 0; r < 4; r++) acc[mi][ni][r] = 0.f;

    const int ktiles = Kdim >> 4;

    // prologue: tile 0 -> buf 0
    {
        cp_async16((uint32_t)__cvta_generic_to_shared(&As[0][am0][ak0]),
                   Ag + (size_t)am0 * Kdim + ak0);
        cp_async16((uint32_t)__cvta_generic_to_shared(&As[0][am1][ak1]),
                   Ag + (size_t)am1 * Kdim + ak1);
        cp_async16((uint32_t)__cvta_generic_to_shared(&Bs[0][bk0][bn0]),
                   Bg + (size_t)bk0 * Ndim + bn0);
        cp_async16((uint32_t)__cvta_generic_to_shared(&Bs[0][bk1][bn0]),
                   Bg + (size_t)bk1 * Ndim + bn0);
        asm volatile("cp.async.commit_group;\n");
    }

    for (int t = 0; t < ktiles; t++) {
        asm volatile("cp.async.wait_group 0;\n");
        __syncthreads();

        if (t + 1 < ktiles) {
            int nb = (t + 1) & 1;
            int k0 = (t + 1) << 4;
            cp_async16((uint32_t)__cvta_generic_to_shared(&As[nb][am0][ak0]),
                       Ag + (size_t)am0 * Kdim + k0 + ak0);
            cp_async16((uint32_t)__cvta_generic_to_shared(&As[nb][am1][ak1]),
                       Ag + (size_t)am1 * Kdim + k0 + ak1);
            cp_async16((uint32_t)__cvta_generic_to_shared(&Bs[nb][bk0][bn0]),
                       Bg + (size_t)(k0 + bk0) * Ndim + bn0);
            cp_async16((uint32_t)__cvta_generic_to_shared(&Bs[nb][bk1][bn0]),
                       Bg + (size_t)(k0 + bk1) * Ndim + bn0);
            asm volatile("cp.async.commit_group;\n");
        }

        const int buf = t & 1;
        #pragma unroll
        for (int s = 0; s < 2; s++) {
            const int k8 = s * 8;
            // A fragments: 4 m-tiles x 4 regs
            uint32_t af[4][4];
            #pragma unroll
            for (int mi = 0; mi < 4; mi++) {
                int rm = warp_m + mi * 16;
                af[mi][0] = f2tf(As[buf][rm + g     ][k8 + tig    ]);
                af[mi][1] = f2tf(As[buf][rm + g + 8 ][k8 + tig    ]);
                af[mi][2] = f2tf(As[buf][rm + g     ][k8 + tig + 4]);
                af[mi][3] = f2tf(As[buf][rm + g + 8 ][k8 + tig + 4]);
            }
            // B fragments: 4 n-tiles x 2 regs
            uint32_t bf[4][2];
            #pragma unroll
            for (int ni = 0; ni < 4; ni++) {
                int cb = warp_n + ni * 8 + g;
                bf[ni][0] = f2tf(Bs[buf][k8 + tig    ][cb]);
                bf[ni][1] = f2tf(Bs[buf][k8 + tig + 4][cb]);
            }
            #pragma unroll
            for (int mi = 0; mi < 4; mi++)
                #pragma unroll
                for (int ni = 0; ni < 4; ni++) {
                    asm volatile(
                        "mma.sync.aligned.m16n8k8.row.col.f32.tf32.tf32.f32 "
                        "{%0,%1,%2,%3}, {%4,%5,%6,%7}, {%8,%9}, {%0,%1,%2,%3};"
                        : "+f"(acc[mi][ni][0]), "+f"(acc[mi][ni][1]),
                          "+f"(acc[mi][ni][2]), "+f"(acc[mi][ni][3])
                        : "r"(af[mi][0]), "r"(af[mi][1]),
                          "r"(af[mi][2]), "r"(af[mi][3]),
                          "r"(bf[ni][0]), "r"(bf[ni][1]));
                }
        }
        __syncthreads();
    }

    // epilogue
    #pragma unroll
    for (int mi = 0; mi < 4; mi++) {
        int row0 = cRow + warp_m + mi * 16 + g;
        #pragma unroll
        for (int ni = 0; ni < 4; ni++) {
            int col = cCol + warp_n + ni * 8 + 2 * tig;
            float2 v0 = make_float2(acc[mi][ni][0], acc[mi][ni][1]);
            float2 v1 = make_float2(acc[mi][ni][2], acc[mi][ni][3]);
            if (bias) {
                float2 bb = *(const float2*)(bias + col);
                v0.x += bb.x; v0.y += bb.y;
                v1.x += bb.x; v1.y += bb.y;
            }
            if (relu) {
                v0.x = fmaxf(v0.x, 0.f); v0.y = fmaxf(v0.y, 0.f);
                v1.x = fmaxf(v1.x, 0.f); v1.y = fmaxf(v1.y, 0.f);
            }
            *(float2*)(C + (size_t)row0       * Ndim + col) = v0;
            *(float2*)(C + (size_t)(row0 + 8) * Ndim + col) = v1;
        }
    }
}

// ---------------- attention: per (b,h) CTA, full softmax, Q=K=V ----------------
#define KS_ROWS 320
#define KS_LD   65
#define ATTN_SMEM ((KS_ROWS*KS_LD + 8*NN) * 4)

__global__ __launch_bounds__(256)
void attn_kernel(const float* __restrict__ k, float* __restrict__ o)
{
    extern __shared__ float sm[];
    float* Ks = sm;                       // KS_ROWS * KS_LD
    float* Aw = sm + KS_ROWS * KS_LD;     // 8 * NN

    int bh = blockIdx.x;
    int b  = bh / HH, h = bh % HH;
    const float* kbase = k + (size_t)b * NN * DDIM + h * DHD;

    int tid  = threadIdx.x;
    int lane = tid & 31;
    int w    = tid >> 5;

    for (int i = tid; i < KS_ROWS * DHD; i += 256) {
        int m = i >> 6, e = i & 63;
        Ks[m * KS_LD + e] = (m < NN) ? kbase[(size_t)m * DDIM + e] : 0.f;
    }
    __syncthreads();

    float* aw = Aw + w * NN;
    const float scale = 0.04419417382415922f;   // 1/sqrt(512)

    for (int n = w; n < NN; n += 8) {
        float sv[10];
        #pragma unroll
        for (int j = 0; j < 10; j++) sv[j] = 0.f;
        const float* qrow = Ks + n * KS_LD;
        #pragma unroll 4
        for (int e = 0; e < 64; e++) {
            float qe = qrow[e];
            #pragma unroll
            for (int j = 0; j < 10; j++)
                sv[j] += qe * Ks[(j * 32 + lane) * KS_LD + e];
        }
        float mx = -1e30f;
        #pragma unroll
        for (int j = 0; j < 10; j++) {
            int m = j * 32 + lane;
            float s = (m < NN) ? sv[j] * scale : -1e30f;
            sv[j] = s;
            mx = fmaxf(mx, s);
        }
        #pragma unroll
        for (int off = 16; off; off >>= 1)
            mx = fmaxf(mx, __shfl_xor_sync(0xffffffffu, mx, off));
        float sum = 0.f;
        #pragma unroll
        for (int j = 0; j < 10; j++) {
            float ev = __expf(sv[j] - mx);
            sv[j] = ev;
            sum += ev;
        }
        #pragma unroll
        for (int off = 16; off; off >>= 1)
            sum += __shfl_xor_sync(0xffffffffu, sum, off);
        float inv = 1.f / sum;

        __syncwarp();
        #pragma unroll
        for (int j = 0; j < 10; j++) {
            int m = j * 32 + lane;
            if (m < NN) aw[m] = sv[j] * inv;
        }
        __syncwarp();

        float o0 = 0.f, o1 = 0.f;
        #pragma unroll 4
        for (int m = 0; m < NN; m++) {
            float a = aw[m];
            o0 += a * Ks[m * KS_LD + lane];
            o1 += a * Ks[m * KS_LD + 32 + lane];
        }
        float* orow = o + (size_t)(b * NN + n) * DDIM + h * DHD;
        orow[lane]      = o0;
        orow[lane + 32] = o1;
        __syncwarp();
    }
}

// ---------------- residual + LayerNorm ----------------
__global__ __launch_bounds__(256)
void ln_kernel(const float* __restrict__ a, const float* __restrict__ b,
               const float* __restrict__ gamma, const float* __restrict__ beta,
               float* __restrict__ out)
{
    int w    = threadIdx.x >> 5;
    int lane = threadIdx.x & 31;
    int row  = blockIdx.x * 8 + w;

    const float4* a4 = (const float4*)(a + (size_t)row * DDIM);
    const float4* b4 = (const float4*)(b + (size_t)row * DDIM);
    float4 v[4];
    float s1 = 0.f, s2 = 0.f;
    #pragma unroll
    for (int j = 0; j < 4; j++) {
        float4 av = a4[j * 32 + lane];
        float4 bv = b4[j * 32 + lane];
        float4 t = make_float4(av.x + bv.x, av.y + bv.y, av.z + bv.z, av.w + bv.w);
        v[j] = t;
        s1 += t.x + t.y + t.z + t.w;
        s2 += t.x * t.x + t.y * t.y + t.z * t.z + t.w * t.w;
    }
    #pragma unroll
    for (int off = 16; off; off >>= 1) {
        s1 += __shfl_xor_sync(0xffffffffu, s1, off);
        s2 += __shfl_xor_sync(0xffffffffu, s2, off);
    }
    float mean = s1 * (1.f / DDIM);
    float var  = s2 * (1.f / DDIM) - mean * mean;
    float rs   = rsqrtf(var + 1e-5f);

    const float4* g4  = (const float4*)gamma;
    const float4* be4 = (const float4*)beta;
    float4* o4 = (float4*)(out + (size_t)row * DDIM);
    #pragma unroll
    for (int j = 0; j < 4; j++) {
        float4 g = g4[j * 32 + lane];
        float4 be = be4[j * 32 + lane];
        float4 t = v[j];
        float4 r;
        r.x = (t.x - mean) * rs * g.x + be.x;
        r.y = (t.y - mean) * rs * g.y + be.y;
        r.z = (t.z - mean) * rs * g.z + be.z;
        r.w = (t.w - mean) * rs * g.w + be.w;
        o4[j * 32 + lane] = r;
    }
}

// ---------------- launcher ----------------
extern "C" void kernel_launch(void* const* d_in, const int* in_sizes, int n_in,
                              void* d_out, int out_size)
{
    const int*   tokens = (const int*)  d_in[0];
    const float* emb    = (const float*)d_in[1];
    const float* pos    = (const float*)d_in[2];
    const float* Wk     = (const float*)d_in[3];
    const float* Wo     = (const float*)d_in[4];
    const float* W1     = (const float*)d_in[5];
    const float* b1     = (const float*)d_in[6];
    const float* W2     = (const float*)d_in[7];
    const float* b2     = (const float*)d_in[8];
    const float* gamma  = (const float*)d_in[9];
    const float* beta   = (const float*)d_in[10];

    float *x, *k, *o, *z, *h, *wp;
    cudaGetSymbolAddress((void**)&x,  g_x);
    cudaGetSymbolAddress((void**)&k,  g_k);
    cudaGetSymbolAddress((void**)&o,  g_o);
    cudaGetSymbolAddress((void**)&z,  g_z);
    cudaGetSymbolAddress((void**)&h,  g_h);
    cudaGetSymbolAddress((void**)&wp, g_wp);

    cudaFuncSetAttribute(attn_kernel,
                         cudaFuncAttributeMaxDynamicSharedMemorySize, ATTN_SMEM);

    embed_kernel<<<(MM * 128) / 256, 256>>>(tokens, emb, pos, x);

    for (int l = 0; l < LLAY; l++) {
        pack_wk<<<(DDIM * DDIM) / 256, 256>>>(Wk + (size_t)l * HH * DDIM * DHD, wp);

        // K = X @ Wpack   [MM, 512]
        mma_gemm_kernel<<<dim3(DDIM / 128, MM / 128), 256>>>(
            x, wp, k, MM, DDIM, DDIM, nullptr, 0);

        // attention -> o  [MM, 512]
        attn_kernel<<<BB * HH, 256, ATTN_SMEM>>>(k, o);

        // o @ Wo -> h
        mma_gemm_kernel<<<dim3(DDIM / 128, MM / 128), 256>>>(
            o, Wo + (size_t)l * DDIM * DDIM, h, MM, DDIM, DDIM, nullptr, 0);

        // z = LN(h + x)
        ln_kernel<<<MM / 8, 256>>>(h, x, gamma + (size_t)l * DDIM,
                                   beta + (size_t)l * DDIM, z);

        // h = relu(z @ W1 + b1)   [MM, 2048]
        mma_gemm_kernel<<<dim3(DFF / 128, MM / 128), 256>>>(
            z, W1 + (size_t)l * DDIM * DFF, h, MM, DFF, DDIM,
            b1 + (size_t)l * DFF, 1);

        // k = h @ W2 + b2   [MM, 512]
        mma_gemm_kernel<<<dim3(DDIM / 128, MM / 128), 256>>>(
            h, W2 + (size_t)l * DFF * DDIM, k, MM, DDIM, DFF,
            b2 + (size_t)l * DDIM, 0);

        // x = LN(k + z)
        float* dst = (l == LLAY - 1) ? (float*)d_out : x;
        ln_kernel<<<MM / 8, 256>>>(k, z, gamma + (size_t)l * DDIM,
                                   beta + (size_t)l * DDIM, dst);
    }
}

// round 3
// speedup vs baseline: 3.5099x; 1.7326x over previous
#include <cuda_runtime.h>
#include <cstddef>
#include <cstdint>

// Problem constants
#define BB   64
#define NN   300
#define DDIM 512
#define HH   8
#define DHD  64
#define LLAY 6
#define DFF  2048
#define MM   (BB*NN)   // 19200 rows

// ---------------- scratch (no allocation allowed) ----------------
__device__ float g_x [MM*DDIM];
__device__ float g_k [MM*DDIM];
__device__ float g_o [MM*DDIM];
__device__ float g_z [MM*DDIM];
__device__ float g_h [(size_t)MM*DFF];
__device__ float g_wp[DDIM*DDIM];

__device__ __forceinline__ uint32_t f2tf(float x) {
    uint32_t r;
    asm("cvt.rna.tf32.f32 %0, %1;" : "=r"(r) : "f"(x));
    return r;
}

__device__ __forceinline__ void cp_async16(uint32_t smem_addr, const void* gptr) {
    asm volatile("cp.async.cg.shared.global [%0], [%1], 16;\n"
                 :: "r"(smem_addr), "l"(gptr));
}

#define MMA_TF32(acc, a0,a1,a2,a3, b0,b1)                                   \
    asm volatile(                                                           \
        "mma.sync.aligned.m16n8k8.row.col.f32.tf32.tf32.f32 "               \
        "{%0,%1,%2,%3}, {%4,%5,%6,%7}, {%8,%9}, {%0,%1,%2,%3};"             \
        : "+f"(acc[0]), "+f"(acc[1]), "+f"(acc[2]), "+f"(acc[3])            \
        : "r"(a0), "r"(a1), "r"(a2), "r"(a3), "r"(b0), "r"(b1))

// ---------------- embed: x = emb[tok] + pos ----------------
__global__ void embed_kernel(const int* __restrict__ tok,
                             const float* __restrict__ emb,
                             const float* __restrict__ pos,
                             float* __restrict__ x)
{
    int gid = blockIdx.x * blockDim.x + threadIdx.x;
    int row = gid >> 7;
    int c   = gid & 127;
    int t   = tok[row];
    int n   = row % NN;
    float4 e = ((const float4*)emb)[(size_t)t * 128 + c];
    float4 p = ((const float4*)pos)[(size_t)n * 128 + c];
    ((float4*)x)[gid] = make_float4(e.x + p.x, e.y + p.y, e.z + p.z, e.w + p.w);
}

// ---------------- pack Wk[l] (H,D,DH) -> (D, H*DH) row-major ----------------
__global__ void pack_wk(const float* __restrict__ wk, float* __restrict__ wp)
{
    int idx = blockIdx.x * blockDim.x + threadIdx.x;
    int d = idx >> 9;
    int c = idx & 511;
    wp[idx] = wk[(size_t)(c >> 6) * (DDIM * DHD) + (size_t)d * DHD + (c & 63)];
}

// ---------------- tf32 tensor-core GEMM (unchanged, verified) ----------------
#define ASTRIDE 20
#define BSTRIDE 136

__global__ __launch_bounds__(256)
void mma_gemm_kernel(const float* __restrict__ A, const float* __restrict__ Bm,
                     float* __restrict__ C, int Mdim, int Ndim, int Kdim,
                     const float* __restrict__ bias, int relu)
{
    __shared__ __align__(16) float As[2][128][ASTRIDE];
    __shared__ __align__(16) float Bs[2][16][BSTRIDE];

    const int tid  = threadIdx.x;
    const int lane = tid & 31;
    const int w    = tid >> 5;
    const int g    = lane >> 2;
    const int tig  = lane & 3;

    const int warp_m = (w & 1) * 64;
    const int warp_n = (w >> 1) * 32;

    const int cRow = blockIdx.y * 128;
    const int cCol = blockIdx.x * 128;

    const int am0 = (tid)       >> 2;
    const int ak0 = (tid & 3) * 4;
    const int am1 = (tid + 256) >> 2;
    const int bk0 = tid >> 5;
    const int bn0 = (tid & 31) * 4;
    const int bk1 = bk0 + 8;

    const float* Ag = A + (size_t)cRow * Kdim;
    const float* Bg = Bm + cCol;

    float acc[4][4][4];
    #pragma unroll
    for (int mi = 0; mi < 4; mi++)
        #pragma unroll
        for (int ni = 0; ni < 4; ni++)
            #pragma unroll
            for (int r = 0; r < 4; r++) acc[mi][ni][r] = 0.f;

    const int ktiles = Kdim >> 4;

    {
        cp_async16((uint32_t)__cvta_generic_to_shared(&As[0][am0][ak0]),
                   Ag + (size_t)am0 * Kdim + ak0);
        cp_async16((uint32_t)__cvta_generic_to_shared(&As[0][am1][ak0]),
                   Ag + (size_t)am1 * Kdim + ak0);
        cp_async16((uint32_t)__cvta_generic_to_shared(&Bs[0][bk0][bn0]),
                   Bg + (size_t)bk0 * Ndim + bn0);
        cp_async16((uint32_t)__cvta_generic_to_shared(&Bs[0][bk1][bn0]),
                   Bg + (size_t)bk1 * Ndim + bn0);
        asm volatile("cp.async.commit_group;\n");
    }

    for (int t = 0; t < ktiles; t++) {
        asm volatile("cp.async.wait_group 0;\n");
        __syncthreads();

        if (t + 1 < ktiles) {
            int nb = (t + 1) & 1;
            int k0 = (t + 1) << 4;
            cp_async16((uint32_t)__cvta_generic_to_shared(&As[nb][am0][ak0]),
                       Ag + (size_t)am0 * Kdim + k0 + ak0);
            cp_async16((uint32_t)__cvta_generic_to_shared(&As[nb][am1][ak0]),
                       Ag + (size_t)am1 * Kdim + k0 + ak0);
            cp_async16((uint32_t)__cvta_generic_to_shared(&Bs[nb][bk0][bn0]),
                       Bg + (size_t)(k0 + bk0) * Ndim + bn0);
            cp_async16((uint32_t)__cvta_generic_to_shared(&Bs[nb][bk1][bn0]),
                       Bg + (size_t)(k0 + bk1) * Ndim + bn0);
            asm volatile("cp.async.commit_group;\n");
        }

        const int buf = t & 1;
        #pragma unroll
        for (int s = 0; s < 2; s++) {
            const int k8 = s * 8;
            uint32_t af[4][4];
            #pragma unroll
            for (int mi = 0; mi < 4; mi++) {
                int rm = warp_m + mi * 16;
                af[mi][0] = f2tf(As[buf][rm + g     ][k8 + tig    ]);
                af[mi][1] = f2tf(As[buf][rm + g + 8 ][k8 + tig    ]);
                af[mi][2] = f2tf(As[buf][rm + g     ][k8 + tig + 4]);
                af[mi][3] = f2tf(As[buf][rm + g + 8 ][k8 + tig + 4]);
            }
            uint32_t bf[4][2];
            #pragma unroll
            for (int ni = 0; ni < 4; ni++) {
                int cb = warp_n + ni * 8 + g;
                bf[ni][0] = f2tf(Bs[buf][k8 + tig    ][cb]);
                bf[ni][1] = f2tf(Bs[buf][k8 + tig + 4][cb]);
            }
            #pragma unroll
            for (int mi = 0; mi < 4; mi++)
                #pragma unroll
                for (int ni = 0; ni < 4; ni++)
                    MMA_TF32(acc[mi][ni], af[mi][0], af[mi][1], af[mi][2], af[mi][3],
                             bf[ni][0], bf[ni][1]);
        }
        __syncthreads();
    }

    #pragma unroll
    for (int mi = 0; mi < 4; mi++) {
        int row0 = cRow + warp_m + mi * 16 + g;
        #pragma unroll
        for (int ni = 0; ni < 4; ni++) {
            int col = cCol + warp_n + ni * 8 + 2 * tig;
            float2 v0 = make_float2(acc[mi][ni][0], acc[mi][ni][1]);
            float2 v1 = make_float2(acc[mi][ni][2], acc[mi][ni][3]);
            if (bias) {
                float2 bb = *(const float2*)(bias + col);
                v0.x += bb.x; v0.y += bb.y;
                v1.x += bb.x; v1.y += bb.y;
            }
            if (relu) {
                v0.x = fmaxf(v0.x, 0.f); v0.y = fmaxf(v0.y, 0.f);
                v1.x = fmaxf(v1.x, 0.f); v1.y = fmaxf(v1.y, 0.f);
            }
            *(float2*)(C + (size_t)row0       * Ndim + col) = v0;
            *(float2*)(C + (size_t)(row0 + 8) * Ndim + col) = v1;
        }
    }
}

// ---------------- tensor-core attention ----------------
// One CTA per (b,h). K tile 320x64 (tf32 bits) in smem, stride 68.
// Query blocks of 64: S = Q K^T (mma), softmax, O = P K (mma).
#define KPAD   320
#define KLD    68
#define NPADK  304          // padded key count (38 k8 steps)
#define SLD    316          // Ss stride: 28g+tig conflict-free
#define MQ     64
#define ATTN_SMEM ((KPAD*KLD + MQ*SLD) * 4)

__global__ __launch_bounds__(256)
void attn_mma_kernel(const float* __restrict__ k, float* __restrict__ o)
{
    extern __shared__ uint32_t smu[];
    uint32_t* Ks  = smu;                    // KPAD*KLD tf32 bits
    uint32_t* SsB = smu + KPAD * KLD;       // MQ*SLD  (bits view)
    float*    Ssf = (float*)SsB;            // float view for scores

    const int bh = blockIdx.x;
    const int b  = bh / HH, h = bh % HH;
    const float* kbase = k + (size_t)b * NN * DDIM + h * DHD;

    const int tid  = threadIdx.x;
    const int lane = tid & 31;
    const int w    = tid >> 5;
    const int g    = lane >> 2;
    const int tig  = lane & 3;

    // load K head tile, convert to tf32 bits, zero-pad rows >= NN
    for (int i = tid; i < KPAD * DHD; i += 256) {
        int m = i >> 6, e = i & 63;
        float v = (m < NN) ? kbase[(size_t)m * DDIM + e] : 0.f;
        Ks[m * KLD + e] = f2tf(v);
    }
    __syncthreads();

    const float scale = 0.04419417382415922f;   // 1/sqrt(512)
    const int mi  = w & 3;        // m-tile within 64-query block
    const int nh  = w >> 2;       // 0/1

    for (int it = 0; it < 5; it++) {
        const int q0 = it * MQ;

        // ---- S = Q K^T : warp = (mi, key-half nh*152), 19 n8-tiles ----
        {
            float acc[19][4];
            #pragma unroll
            for (int ni = 0; ni < 19; ni++)
                #pragma unroll
                for (int r = 0; r < 4; r++) acc[ni][r] = 0.f;

            const int ar = (q0 + mi * 16 + g) * KLD;
            const int ncol0 = nh * 152;
            #pragma unroll
            for (int ks = 0; ks < 8; ks++) {
                const int kc = ks * 8;
                uint32_t a0 = Ks[ar            + kc + tig    ];
                uint32_t a1 = Ks[ar + 8 * KLD  + kc + tig    ];
                uint32_t a2 = Ks[ar            + kc + tig + 4];
                uint32_t a3 = Ks[ar + 8 * KLD  + kc + tig + 4];
                #pragma unroll
                for (int ni = 0; ni < 19; ni++) {
                    const int kr = (ncol0 + ni * 8 + g) * KLD + kc;
                    uint32_t b0 = Ks[kr + tig    ];
                    uint32_t b1 = Ks[kr + tig + 4];
                    MMA_TF32(acc[ni], a0, a1, a2, a3, b0, b1);
                }
            }
            // write scores (scaled, key-masked)
            const int row0 = mi * 16 + g;
            #pragma unroll
            for (int ni = 0; ni < 19; ni++) {
                int col = ncol0 + ni * 8 + 2 * tig;
                Ssf[row0 * SLD + col    ] = (col     < NN) ? acc[ni][0] * scale : -1e30f;
                Ssf[row0 * SLD + col + 1] = (col + 1 < NN) ? acc[ni][1] * scale : -1e30f;
                Ssf[(row0+8) * SLD + col    ] = (col     < NN) ? acc[ni][2] * scale : -1e30f;
                Ssf[(row0+8) * SLD + col + 1] = (col + 1 < NN) ? acc[ni][3] * scale : -1e30f;
            }
        }
        __syncthreads();

        // ---- softmax: warp w handles rows [w*8, w*8+8) ----
        for (int r = 0; r < 8; r++) {
            const int row = w * 8 + r;
            float* srow = Ssf + row * SLD;
            float v[10];
            float mx = -1e30f;
            #pragma unroll
            for (int j = 0; j < 10; j++) {
                int c = lane + 32 * j;
                float s = (c < NPADK) ? srow[c] : -1e30f;
                v[j] = s;
                mx = fmaxf(mx, s);
            }
            #pragma unroll
            for (int off = 16; off; off >>= 1)
                mx = fmaxf(mx, __shfl_xor_sync(0xffffffffu, mx, off));
            float sum = 0.f;
            #pragma unroll
            for (int j = 0; j < 10; j++) {
                float ev = __expf(v[j] - mx);
                v[j] = ev;
                sum += ev;
            }
            #pragma unroll
            for (int off = 16; off; off >>= 1)
                sum += __shfl_xor_sync(0xffffffffu, sum, off);
            float inv = 1.f / sum;
            #pragma unroll
            for (int j = 0; j < 10; j++) {
                int c = lane + 32 * j;
                if (c < NPADK)
                    SsB[row * SLD + c] = f2tf(v[j] * inv);   // p as tf32 bits
            }
        }
        __syncthreads();

        // ---- O = P K : warp = (mi, channel-half nh*32), 4 n8-tiles ----
        {
            float oacc[4][4];
            #pragma unroll
            for (int ni = 0; ni < 4; ni++)
                #pragma unroll
                for (int r = 0; r < 4; r++) oacc[ni][r] = 0.f;

            const int ar = (mi * 16 + g) * SLD;
            #pragma unroll 2
            for (int ks = 0; ks < 38; ks++) {
                const int kc = ks * 8;
                uint32_t a0 = SsB[ar           + kc + tig    ];
                uint32_t a1 = SsB[ar + 8 * SLD + kc + tig    ];
                uint32_t a2 = SsB[ar           + kc + tig + 4];
                uint32_t a3 = SsB[ar + 8 * SLD + kc + tig + 4];
                #pragma unroll
                for (int ni = 0; ni < 4; ni++) {
                    const int ch = nh * 32 + ni * 8 + g;
                    uint32_t b0 = Ks[(kc + tig    ) * KLD + ch];
                    uint32_t b1 = Ks[(kc + tig + 4) * KLD + ch];
                    MMA_TF32(oacc[ni], a0, a1, a2, a3, b0, b1);
                }
            }
            const int q = q0 + mi * 16 + g;
            float* ob = o + (size_t)b * NN * DDIM + h * DHD;
            #pragma unroll
            for (int ni = 0; ni < 4; ni++) {
                int ch = nh * 32 + ni * 8 + 2 * tig;
                if (q < NN)
                    *(float2*)(ob + (size_t)q * DDIM + ch) =
                        make_float2(oacc[ni][0], oacc[ni][1]);
                if (q + 8 < NN)
                    *(float2*)(ob + (size_t)(q + 8) * DDIM + ch) =
                        make_float2(oacc[ni][2], oacc[ni][3]);
            }
        }
        __syncthreads();
    }
}

// ---------------- residual + LayerNorm ----------------
__global__ __launch_bounds__(256)
void ln_kernel(const float* __restrict__ a, const float* __restrict__ b,
               const float* __restrict__ gamma, const float* __restrict__ beta,
               float* __restrict__ out)
{
    int w    = threadIdx.x >> 5;
    int lane = threadIdx.x & 31;
    int row  = blockIdx.x * 8 + w;

    const float4* a4 = (const float4*)(a + (size_t)row * DDIM);
    const float4* b4 = (const float4*)(b + (size_t)row * DDIM);
    float4 v[4];
    float s1 = 0.f, s2 = 0.f;
    #pragma unroll
    for (int j = 0; j < 4; j++) {
        float4 av = a4[j * 32 + lane];
        float4 bv = b4[j * 32 + lane];
        float4 t = make_float4(av.x + bv.x, av.y + bv.y, av.z + bv.z, av.w + bv.w);
        v[j] = t;
        s1 += t.x + t.y + t.z + t.w;
        s2 += t.x * t.x + t.y * t.y + t.z * t.z + t.w * t.w;
    }
    #pragma unroll
    for (int off = 16; off; off >>= 1) {
        s1 += __shfl_xor_sync(0xffffffffu, s1, off);
        s2 += __shfl_xor_sync(0xffffffffu, s2, off);
    }
    float mean = s1 * (1.f / DDIM);
    float var  = s2 * (1.f / DDIM) - mean * mean;
    float rs   = rsqrtf(var + 1e-5f);

    const float4* g4  = (const float4*)gamma;
    const float4* be4 = (const float4*)beta;
    float4* o4 = (float4*)(out + (size_t)row * DDIM);
    #pragma unroll
    for (int j = 0; j < 4; j++) {
        float4 g = g4[j * 32 + lane];
        float4 be = be4[j * 32 + lane];
        float4 t = v[j];
        float4 r;
        r.x = (t.x - mean) * rs * g.x + be.x;
        r.y = (t.y - mean) * rs * g.y + be.y;
        r.z = (t.z - mean) * rs * g.z + be.z;
        r.w = (t.w - mean) * rs * g.w + be.w;
        o4[j * 32 + lane] = r;
    }
}

// ---------------- launcher ----------------
extern "C" void kernel_launch(void* const* d_in, const int* in_sizes, int n_in,
                              void* d_out, int out_size)
{
    const int*   tokens = (const int*)  d_in[0];
    const float* emb    = (const float*)d_in[1];
    const float* pos    = (const float*)d_in[2];
    const float* Wk     = (const float*)d_in[3];
    const float* Wo     = (const float*)d_in[4];
    const float* W1     = (const float*)d_in[5];
    const float* b1     = (const float*)d_in[6];
    const float* W2     = (const float*)d_in[7];
    const float* b2     = (const float*)d_in[8];
    const float* gamma  = (const float*)d_in[9];
    const float* beta   = (const float*)d_in[10];

    float *x, *k, *o, *z, *h, *wp;
    cudaGetSymbolAddress((void**)&x,  g_x);
    cudaGetSymbolAddress((void**)&k,  g_k);
    cudaGetSymbolAddress((void**)&o,  g_o);
    cudaGetSymbolAddress((void**)&z,  g_z);
    cudaGetSymbolAddress((void**)&h,  g_h);
    cudaGetSymbolAddress((void**)&wp, g_wp);

    cudaFuncSetAttribute(attn_mma_kernel,
                         cudaFuncAttributeMaxDynamicSharedMemorySize, ATTN_SMEM);

    embed_kernel<<<(MM * 128) / 256, 256>>>(tokens, emb, pos, x);

    for (int l = 0; l < LLAY; l++) {
        pack_wk<<<(DDIM * DDIM) / 256, 256>>>(Wk + (size_t)l * HH * DDIM * DHD, wp);

        mma_gemm_kernel<<<dim3(DDIM / 128, MM / 128), 256>>>(
            x, wp, k, MM, DDIM, DDIM, nullptr, 0);

        attn_mma_kernel<<<BB * HH, 256, ATTN_SMEM>>>(k, o);

        mma_gemm_kernel<<<dim3(DDIM / 128, MM / 128), 256>>>(
            o, Wo + (size_t)l * DDIM * DDIM, h, MM, DDIM, DDIM, nullptr, 0);

        ln_kernel<<<MM / 8, 256>>>(h, x, gamma + (size_t)l * DDIM,
                                   beta + (size_t)l * DDIM, z);

        mma_gemm_kernel<<<dim3(DFF / 128, MM / 128), 256>>>(
            z, W1 + (size_t)l * DDIM * DFF, h, MM, DFF, DDIM,
            b1 + (size_t)l * DFF, 1);

        mma_gemm_kernel<<<dim3(DDIM / 128, MM / 128), 256>>>(
            h, W2 + (size_t)l * DFF * DDIM, k, MM, DDIM, DFF,
            b2 + (size_t)l * DDIM, 0);

        float* dst = (l == LLAY - 1) ? (float*)d_out : x;
        ln_kernel<<<MM / 8, 256>>>(k, z, gamma + (size_t)l * DDIM,
                                   beta + (size_t)l * DDIM, dst);
    }
}

// round 4
// speedup vs baseline: 3.6276x; 1.0335x over previous
#include <cuda_runtime.h>
#include <cstddef>
#include <cstdint>

// Problem constants
#define BB   64
#define NN   300
#define DDIM 512
#define HH   8
#define DHD  64
#define LLAY 6
#define DFF  2048
#define MM   (BB*NN)   // 19200 rows

// ---------------- scratch (no allocation allowed) ----------------
__device__ float g_x [MM*DDIM];
__device__ float g_k [MM*DDIM];
__device__ float g_o [MM*DDIM];
__device__ float g_z [MM*DDIM];
__device__ float g_h [(size_t)MM*DFF];
__device__ float g_wp[DDIM*DDIM];

__device__ __forceinline__ uint32_t f2tf(float x) {
    uint32_t r;
    asm("cvt.rna.tf32.f32 %0, %1;" : "=r"(r) : "f"(x));
    return r;
}

__device__ __forceinline__ void cp_async16(uint32_t smem_addr, const void* gptr) {
    asm volatile("cp.async.cg.shared.global [%0], [%1], 16;\n"
                 :: "r"(smem_addr), "l"(gptr));
}

#define MMA_TF32(acc, a0,a1,a2,a3, b0,b1)                                   \
    asm volatile(                                                           \
        "mma.sync.aligned.m16n8k8.row.col.f32.tf32.tf32.f32 "               \
        "{%0,%1,%2,%3}, {%4,%5,%6,%7}, {%8,%9}, {%0,%1,%2,%3};"             \
        : "+f"(acc[0]), "+f"(acc[1]), "+f"(acc[2]), "+f"(acc[3])            \
        : "r"(a0), "r"(a1), "r"(a2), "r"(a3), "r"(b0), "r"(b1))

#define LDSM_X4(r0,r1,r2,r3, addr)                                          \
    asm volatile(                                                           \
        "ldmatrix.sync.aligned.m8n8.x4.shared.b16 {%0,%1,%2,%3}, [%4];"     \
        : "=r"(r0), "=r"(r1), "=r"(r2), "=r"(r3) : "r"(addr))

// ---------------- embed: x = emb[tok] + pos ----------------
__global__ void embed_kernel(const int* __restrict__ tok,
                             const float* __restrict__ emb,
                             const float* __restrict__ pos,
                             float* __restrict__ x)
{
    int gid = blockIdx.x * blockDim.x + threadIdx.x;
    int row = gid >> 7;
    int c   = gid & 127;
    int t   = tok[row];
    int n   = row % NN;
    float4 e = ((const float4*)emb)[(size_t)t * 128 + c];
    float4 p = ((const float4*)pos)[(size_t)n * 128 + c];
    ((float4*)x)[gid] = make_float4(e.x + p.x, e.y + p.y, e.z + p.z, e.w + p.w);
}

// ---------------- pack Wk[l] (H,D,DH) -> (D, H*DH) row-major ----------------
__global__ void pack_wk(const float* __restrict__ wk, float* __restrict__ wp)
{
    int idx = blockIdx.x * blockDim.x + threadIdx.x;
    int d = idx >> 9;
    int c = idx & 511;
    wp[idx] = wk[(size_t)(c >> 6) * (DDIM * DHD) + (size_t)d * DHD + (c & 63)];
}

// ---------------- tf32 tensor-core GEMM ----------------
#define ASTRIDE 20
#define BSTRIDE 136
#define A_STAGE (128*ASTRIDE*4)

__global__ __launch_bounds__(256)
void mma_gemm_kernel(const float* __restrict__ A, const float* __restrict__ Bm,
                     float* __restrict__ C, int Mdim, int Ndim, int Kdim,
                     const float* __restrict__ bias, int relu)
{
    __shared__ __align__(16) float As[2][128][ASTRIDE];
    __shared__ __align__(16) float Bs[2][16][BSTRIDE];

    const int tid  = threadIdx.x;
    const int lane = tid & 31;
    const int w    = tid >> 5;
    const int g    = lane >> 2;
    const int tig  = lane & 3;

    const int warp_m = (w & 1) * 64;
    const int warp_n = (w >> 1) * 32;

    const int cRow = blockIdx.y * 128;
    const int cCol = blockIdx.x * 128;

    const int am0 = (tid)       >> 2;
    const int ak0 = (tid & 3) * 4;
    const int am1 = (tid + 256) >> 2;
    const int bk0 = tid >> 5;
    const int bn0 = (tid & 31) * 4;
    const int bk1 = bk0 + 8;

    const float* Ag = A + (size_t)cRow * Kdim;
    const float* Bg = Bm + cCol;

    // ldmatrix A address (per thread), within stage 0
    const uint32_t as_base = (uint32_t)__cvta_generic_to_shared(&As[0][0][0]);
    const uint32_t a_ld_off =
        ((uint32_t)(warp_m + (lane & 15)) * ASTRIDE + ((lane >> 4) << 2)) * 4;

    float acc[4][4][4];
    #pragma unroll
    for (int mi = 0; mi < 4; mi++)
        #pragma unroll
        for (int ni = 0; ni < 4; ni++)
            #pragma unroll
            for (int r = 0; r < 4; r++) acc[mi][ni][r] = 0.f;

    const int ktiles = Kdim >> 4;

    // prologue: tile 0 -> buf 0
    {
        cp_async16((uint32_t)__cvta_generic_to_shared(&As[0][am0][ak0]),
                   Ag + (size_t)am0 * Kdim + ak0);
        cp_async16((uint32_t)__cvta_generic_to_shared(&As[0][am1][ak0]),
                   Ag + (size_t)am1 * Kdim + ak0);
        cp_async16((uint32_t)__cvta_generic_to_shared(&Bs[0][bk0][bn0]),
                   Bg + (size_t)bk0 * Ndim + bn0);
        cp_async16((uint32_t)__cvta_generic_to_shared(&Bs[0][bk1][bn0]),
                   Bg + (size_t)bk1 * Ndim + bn0);
        asm volatile("cp.async.commit_group;\n");
    }

    for (int t = 0; t < ktiles; t++) {
        // prefetch t+1 first, then wait for t only
        if (t + 1 < ktiles) {
            int nb = (t + 1) & 1;
            int k0 = (t + 1) << 4;
            cp_async16((uint32_t)__cvta_generic_to_shared(&As[nb][am0][ak0]),
                       Ag + (size_t)am0 * Kdim + k0 + ak0);
            cp_async16((uint32_t)__cvta_generic_to_shared(&As[nb][am1][ak0]),
                       Ag + (size_t)am1 * Kdim + k0 + ak0);
            cp_async16((uint32_t)__cvta_generic_to_shared(&Bs[nb][bk0][bn0]),
                       Bg + (size_t)(k0 + bk0) * Ndim + bn0);
            cp_async16((uint32_t)__cvta_generic_to_shared(&Bs[nb][bk1][bn0]),
                       Bg + (size_t)(k0 + bk1) * Ndim + bn0);
            asm volatile("cp.async.commit_group;\n");
            asm volatile("cp.async.wait_group 1;\n");
        } else {
            asm volatile("cp.async.wait_group 0;\n");
        }
        __syncthreads();

        const int buf = t & 1;
        const uint32_t a_stage = as_base + (uint32_t)buf * A_STAGE + a_ld_off;
        #pragma unroll
        for (int s = 0; s < 2; s++) {
            const int k8 = s * 8;
            uint32_t af[4][4];
            #pragma unroll
            for (int mi = 0; mi < 4; mi++) {
                uint32_t r0, r1, r2, r3;
                LDSM_X4(r0, r1, r2, r3,
                        a_stage + (uint32_t)(mi * 16 * ASTRIDE + k8) * 4);
                af[mi][0] = f2tf(__uint_as_float(r0));
                af[mi][1] = f2tf(__uint_as_float(r1));
                af[mi][2] = f2tf(__uint_as_float(r2));
                af[mi][3] = f2tf(__uint_as_float(r3));
            }
            uint32_t bf[4][2];
            #pragma unroll
            for (int ni = 0; ni < 4; ni++) {
                int cb = warp_n + ni * 8 + g;
                bf[ni][0] = f2tf(Bs[buf][k8 + tig    ][cb]);
                bf[ni][1] = f2tf(Bs[buf][k8 + tig + 4][cb]);
            }
            #pragma unroll
            for (int mi = 0; mi < 4; mi++)
                #pragma unroll
                for (int ni = 0; ni < 4; ni++)
                    MMA_TF32(acc[mi][ni], af[mi][0], af[mi][1], af[mi][2], af[mi][3],
                             bf[ni][0], bf[ni][1]);
        }
        __syncthreads();
    }

    #pragma unroll
    for (int mi = 0; mi < 4; mi++) {
        int row0 = cRow + warp_m + mi * 16 + g;
        #pragma unroll
        for (int ni = 0; ni < 4; ni++) {
            int col = cCol + warp_n + ni * 8 + 2 * tig;
            float2 v0 = make_float2(acc[mi][ni][0], acc[mi][ni][1]);
            float2 v1 = make_float2(acc[mi][ni][2], acc[mi][ni][3]);
            if (bias) {
                float2 bb = *(const float2*)(bias + col);
                v0.x += bb.x; v0.y += bb.y;
                v1.x += bb.x; v1.y += bb.y;
            }
            if (relu) {
                v0.x = fmaxf(v0.x, 0.f); v0.y = fmaxf(v0.y, 0.f);
                v1.x = fmaxf(v1.x, 0.f); v1.y = fmaxf(v1.y, 0.f);
            }
            *(float2*)(C + (size_t)row0       * Ndim + col) = v0;
            *(float2*)(C + (size_t)(row0 + 8) * Ndim + col) = v1;
        }
    }
}

// ---------------- tensor-core attention (512 threads, ldmatrix) ----------------
// One CTA per (b,h). K tile 320x64 tf32 bits in smem (stride 68).
// 5 query blocks of 64. S = Q K^T (16 warps: 4 m-tiles x 4 key-quarters of 80),
// softmax (16 warps x 4 rows), O = P K (4 m-tiles x 4 channel-quarters of 16).
#define KPAD   320
#define KLD    68
#define SLD    324
#define MQ     64
#define ATTN_SMEM ((KPAD*KLD + MQ*SLD) * 4)

__global__ __launch_bounds__(512)
void attn_mma_kernel(const float* __restrict__ k, float* __restrict__ o)
{
    extern __shared__ uint32_t smu[];
    uint32_t* Ks  = smu;                    // KPAD*KLD tf32 bits
    uint32_t* SsB = smu + KPAD * KLD;       // MQ*SLD (bits view)
    float*    Ssf = (float*)SsB;            // float view for scores

    const int bh = blockIdx.x;
    const int b  = bh / HH, h = bh % HH;
    const float* kbase = k + (size_t)b * NN * DDIM + h * DHD;

    const int tid  = threadIdx.x;
    const int lane = tid & 31;
    const int w    = tid >> 5;      // 0..15
    const int g    = lane >> 2;
    const int tig  = lane & 3;

    const uint32_t ks_addr = (uint32_t)__cvta_generic_to_shared(Ks);
    const uint32_t ss_addr = (uint32_t)__cvta_generic_to_shared(SsB);

    // load K head tile as tf32 bits, zero-pad rows >= NN
    for (int i = tid; i < KPAD * DHD; i += 512) {
        int m = i >> 6, e = i & 63;
        float v = (m < NN) ? kbase[(size_t)m * DDIM + e] : 0.f;
        Ks[m * KLD + e] = f2tf(v);
    }
    __syncthreads();

    const float scale = 0.04419417382415922f;   // 1/sqrt(512)
    const int mi  = w & 3;        // m-tile (16 queries)
    const int qtr = w >> 2;       // quarter (80 keys / 16 channels)

    // per-thread ldmatrix offsets
    const uint32_t a_row  = (uint32_t)(mi * 16 + (lane & 15));
    const uint32_t a_coff = (uint32_t)((lane >> 4) << 2);
    const uint32_t b_row  = (uint32_t)(qtr * 80 + (lane & 7) + ((lane & 16) >> 1));
    const uint32_t b_coff = (uint32_t)((lane & 8) >> 1);

    for (int it = 0; it < 5; it++) {
        const int q0 = it * MQ;

        // ---- S = Q K^T : 10 n8-tiles per warp ----
        {
            float acc[10][4];
            #pragma unroll
            for (int ni = 0; ni < 10; ni++)
                #pragma unroll
                for (int r = 0; r < 4; r++) acc[ni][r] = 0.f;

            const uint32_t a_base = ks_addr + ((q0 + a_row) * KLD + a_coff) * 4;
            const uint32_t b_base = ks_addr + (b_row * KLD + b_coff) * 4;

            #pragma unroll
            for (int ks = 0; ks < 8; ks++) {
                const uint32_t kc4 = (uint32_t)(ks * 8) * 4;
                uint32_t a0, a1, a2, a3;
                LDSM_X4(a0, a1, a2, a3, a_base + kc4);
                #pragma unroll
                for (int p = 0; p < 5; p++) {
                    uint32_t b0, b1, b2, b3;
                    LDSM_X4(b0, b1, b2, b3,
                            b_base + (uint32_t)(p * 16 * KLD) * 4 + kc4);
                    MMA_TF32(acc[2*p    ], a0, a1, a2, a3, b0, b1);
                    MMA_TF32(acc[2*p + 1], a0, a1, a2, a3, b2, b3);
                }
            }
            const int row0 = mi * 16 + g;
            #pragma unroll
            for (int ni = 0; ni < 10; ni++) {
                int col = qtr * 80 + ni * 8 + 2 * tig;
                Ssf[row0 * SLD + col    ] = (col     < NN) ? acc[ni][0] * scale : -1e30f;
                Ssf[row0 * SLD + col + 1] = (col + 1 < NN) ? acc[ni][1] * scale : -1e30f;
                Ssf[(row0+8) * SLD + col    ] = (col     < NN) ? acc[ni][2] * scale : -1e30f;
                Ssf[(row0+8) * SLD + col + 1] = (col + 1 < NN) ? acc[ni][3] * scale : -1e30f;
            }
        }
        __syncthreads();

        // ---- softmax: warp w -> rows [4w, 4w+4), 320 cols ----
        #pragma unroll
        for (int r = 0; r < 4; r++) {
            const int row = w * 4 + r;
            float* srow = Ssf + row * SLD;
            float v[10];
            float mx = -1e30f;
            #pragma unroll
            for (int j = 0; j < 10; j++) {
                float s = srow[lane + 32 * j];
                v[j] = s;
                mx = fmaxf(mx, s);
            }
            #pragma unroll
            for (int off = 16; off; off >>= 1)
                mx = fmaxf(mx, __shfl_xor_sync(0xffffffffu, mx, off));
            float sum = 0.f;
            #pragma unroll
            for (int j = 0; j < 10; j++) {
                float ev = __expf(v[j] - mx);
                v[j] = ev;
                sum += ev;
            }
            #pragma unroll
            for (int off = 16; off; off >>= 1)
                sum += __shfl_xor_sync(0xffffffffu, sum, off);
            float inv = 1.f / sum;
            #pragma unroll
            for (int j = 0; j < 10; j++)
                SsB[row * SLD + lane + 32 * j] = f2tf(v[j] * inv);
        }
        __syncthreads();

        // ---- O = P K : 2 n8-tiles per warp (16 channels) ----
        {
            float oacc[2][4];
            #pragma unroll
            for (int ni = 0; ni < 2; ni++)
                #pragma unroll
                for (int r = 0; r < 4; r++) oacc[ni][r] = 0.f;

            const uint32_t pa_base = ss_addr + (a_row * SLD + a_coff) * 4;

            #pragma unroll 4
            for (int ks = 0; ks < 40; ks++) {
                const int kc = ks * 8;
                uint32_t a0, a1, a2, a3;
                LDSM_X4(a0, a1, a2, a3, pa_base + (uint32_t)kc * 4);
                #pragma unroll
                for (int ni = 0; ni < 2; ni++) {
                    const int ch = qtr * 16 + ni * 8 + g;
                    uint32_t b0 = Ks[(kc + tig    ) * KLD + ch];
                    uint32_t b1 = Ks[(kc + tig + 4) * KLD + ch];
                    MMA_TF32(oacc[ni], a0, a1, a2, a3, b0, b1);
                }
            }
            const int q = q0 + mi * 16 + g;
            float* ob = o + (size_t)b * NN * DDIM + h * DHD;
            #pragma unroll
            for (int ni = 0; ni < 2; ni++) {
                int ch = qtr * 16 + ni * 8 + 2 * tig;
                if (q < NN)
                    *(float2*)(ob + (size_t)q * DDIM + ch) =
                        make_float2(oacc[ni][0], oacc[ni][1]);
                if (q + 8 < NN)
                    *(float2*)(ob + (size_t)(q + 8) * DDIM + ch) =
                        make_float2(oacc[ni][2], oacc[ni][3]);
            }
        }
        __syncthreads();
    }
}

// ---------------- residual + LayerNorm ----------------
__global__ __launch_bounds__(256)
void ln_kernel(const float* __restrict__ a, const float* __restrict__ b,
               const float* __restrict__ gamma, const float* __restrict__ beta,
               float* __restrict__ out)
{
    int w    = threadIdx.x >> 5;
    int lane = threadIdx.x & 31;
    int row  = blockIdx.x * 8 + w;

    const float4* a4 = (const float4*)(a + (size_t)row * DDIM);
    const float4* b4 = (const float4*)(b + (size_t)row * DDIM);
    float4 v[4];
    float s1 = 0.f, s2 = 0.f;
    #pragma unroll
    for (int j = 0; j < 4; j++) {
        float4 av = a4[j * 32 + lane];
        float4 bv = b4[j * 32 + lane];
        float4 t = make_float4(av.x + bv.x, av.y + bv.y, av.z + bv.z, av.w + bv.w);
        v[j] = t;
        s1 += t.x + t.y + t.z + t.w;
        s2 += t.x * t.x + t.y * t.y + t.z * t.z + t.w * t.w;
    }
    #pragma unroll
    for (int off = 16; off; off >>= 1) {
        s1 += __shfl_xor_sync(0xffffffffu, s1, off);
        s2 += __shfl_xor_sync(0xffffffffu, s2, off);
    }
    float mean = s1 * (1.f / DDIM);
    float var  = s2 * (1.f / DDIM) - mean * mean;
    float rs   = rsqrtf(var + 1e-5f);

    const float4* g4  = (const float4*)gamma;
    const float4* be4 = (const float4*)beta;
    float4* o4 = (float4*)(out + (size_t)row * DDIM);
    #pragma unroll
    for (int j = 0; j < 4; j++) {
        float4 g = g4[j * 32 + lane];
        float4 be = be4[j * 32 + lane];
        float4 t = v[j];
        float4 r;
        r.x = (t.x - mean) * rs * g.x + be.x;
        r.y = (t.y - mean) * rs * g.y + be.y;
        r.z = (t.z - mean) * rs * g.z + be.z;
        r.w = (t.w - mean) * rs * g.w + be.w;
        o4[j * 32 + lane] = r;
    }
}

// ---------------- launcher ----------------
extern "C" void kernel_launch(void* const* d_in, const int* in_sizes, int n_in,
                              void* d_out, int out_size)
{
    const int*   tokens = (const int*)  d_in[0];
    const float* emb    = (const float*)d_in[1];
    const float* pos    = (const float*)d_in[2];
    const float* Wk     = (const float*)d_in[3];
    const float* Wo     = (const float*)d_in[4];
    const float* W1     = (const float*)d_in[5];
    const float* b1     = (const float*)d_in[6];
    const float* W2     = (const float*)d_in[7];
    const float* b2     = (const float*)d_in[8];
    const float* gamma  = (const float*)d_in[9];
    const float* beta   = (const float*)d_in[10];

    float *x, *k, *o, *z, *h, *wp;
    cudaGetSymbolAddress((void**)&x,  g_x);
    cudaGetSymbolAddress((void**)&k,  g_k);
    cudaGetSymbolAddress((void**)&o,  g_o);
    cudaGetSymbolAddress((void**)&z,  g_z);
    cudaGetSymbolAddress((void**)&h,  g_h);
    cudaGetSymbolAddress((void**)&wp, g_wp);

    cudaFuncSetAttribute(attn_mma_kernel,
                         cudaFuncAttributeMaxDynamicSharedMemorySize, ATTN_SMEM);

    embed_kernel<<<(MM * 128) / 256, 256>>>(tokens, emb, pos, x);

    for (int l = 0; l < LLAY; l++) {
        pack_wk<<<(DDIM * DDIM) / 256, 256>>>(Wk + (size_t)l * HH * DDIM * DHD, wp);

        mma_gemm_kernel<<<dim3(DDIM / 128, MM / 128), 256>>>(
            x, wp, k, MM, DDIM, DDIM, nullptr, 0);

        attn_mma_kernel<<<BB * HH, 512, ATTN_SMEM>>>(k, o);

        mma_gemm_kernel<<<dim3(DDIM / 128, MM / 128), 256>>>(
            o, Wo + (size_t)l * DDIM * DDIM, h, MM, DDIM, DDIM, nullptr, 0);

        ln_kernel<<<MM / 8, 256>>>(h, x, gamma + (size_t)l * DDIM,
                                   beta + (size_t)l * DDIM, z);

        mma_gemm_kernel<<<dim3(DFF / 128, MM / 128), 256>>>(
            z, W1 + (size_t)l * DDIM * DFF, h, MM, DFF, DDIM,
            b1 + (size_t)l * DFF, 1);

        mma_gemm_kernel<<<dim3(DDIM / 128, MM / 128), 256>>>(
            h, W2 + (size_t)l * DFF * DDIM, k, MM, DDIM, DFF,
            b2 + (size_t)l * DDIM, 0);

        float* dst = (l == LLAY - 1) ? (float*)d_out : x;
        ln_kernel<<<MM / 8, 256>>>(k, z, gamma + (size_t)l * DDIM,
                                   beta + (size_t)l * DDIM, dst);
    }
}